// round 3
// baseline (speedup 1.0000x reference)
#include <cuda_runtime.h>

#define NTHREADS 128
#define HID 32
#define NB 4
#define DIN 3

typedef unsigned long long ull;

__device__ __forceinline__ ull fma2(ull a, ull b, ull c) {
    ull d; asm("fma.rn.f32x2 %0, %1, %2, %3;" : "=l"(d) : "l"(a), "l"(b), "l"(c)); return d;
}
__device__ __forceinline__ ull mul2(ull a, ull b) {
    ull d; asm("mul.rn.f32x2 %0, %1, %2;" : "=l"(d) : "l"(a), "l"(b)); return d;
}
__device__ __forceinline__ ull add2(ull a, ull b) {
    ull d; asm("add.rn.f32x2 %0, %1, %2;" : "=l"(d) : "l"(a), "l"(b)); return d;
}
__device__ __forceinline__ ull pack2(float lo, float hi) {
    ull r; asm("mov.b64 %0, {%1, %2};" : "=l"(r) : "f"(lo), "f"(hi)); return r;
}
__device__ __forceinline__ void unpack2(ull v, float& lo, float& hi) {
    asm("mov.b64 {%0, %1}, %2;" : "=f"(lo), "=f"(hi) : "l"(v));
}
__device__ __forceinline__ float ex2a(float x) {
    float y; asm("ex2.approx.f32 %0, %1;" : "=f"(y) : "f"(x)); return y;
}
__device__ __forceinline__ float rcpa(float x) {
    float y; asm("rcp.approx.f32 %0, %1;" : "=f"(y) : "f"(x)); return y;
}

// tanh on a packed f32x2 pair: t = 1 - 2/(exp(2x)+1).
// Saturates correctly: x>>0 -> ex2=inf -> rcp=0 -> 1 ; x<<0 -> ex2=0 -> rcp(1)=1 -> -1.
__device__ __forceinline__ ull tanh2p(ull z) {
    const float C = 2.885390081777927f;  // 2*log2(e)
    ull v = mul2(z, pack2(C, C));
    float a, b; unpack2(v, a, b);
    a = ex2a(a); b = ex2a(b);
    ull e = add2(pack2(a, b), pack2(1.0f, 1.0f));
    float ra, rb; unpack2(e, ra, rb);
    ra = rcpa(ra); rb = rcpa(rb);
    return fma2(pack2(ra, rb), pack2(-2.0f, -2.0f), pack2(1.0f, 1.0f));
}

// 32->32 dense + tanh for TWO points. Hidden state is packed: hp[j] = (h[2j], h[2j+1]).
// Each weight LDS.128 feeds 4 fma2 (2 points x 2 output-pairs).
__device__ __forceinline__ void dense32x2(const float* __restrict__ w,
                                          const float* __restrict__ bias,
                                          ull* __restrict__ hp0, ull* __restrict__ hp1) {
    ull acc0[16], acc1[16];
    const ulonglong2* bb = (const ulonglong2*)bias;
#pragma unroll
    for (int q = 0; q < 8; q++) {
        ulonglong2 t = bb[q];
        acc0[2*q] = t.x; acc0[2*q+1] = t.y;
        acc1[2*q] = t.x; acc1[2*q+1] = t.y;
    }
#pragma unroll
    for (int j = 0; j < 16; j++) {
        float l0, u0, l1, u1;
        unpack2(hp0[j], l0, u0);
        unpack2(hp1[j], l1, u1);
        ull a0 = pack2(l0, l0), b0 = pack2(u0, u0);
        ull a1 = pack2(l1, l1), b1 = pack2(u1, u1);
        const ulonglong2* wr0 = (const ulonglong2*)(w + (2*j) * HID);
        const ulonglong2* wr1 = (const ulonglong2*)(w + (2*j+1) * HID);
#pragma unroll
        for (int q = 0; q < 8; q++) {
            ulonglong2 wv0 = wr0[q];
            acc0[2*q]   = fma2(a0, wv0.x, acc0[2*q]);
            acc0[2*q+1] = fma2(a0, wv0.y, acc0[2*q+1]);
            acc1[2*q]   = fma2(a1, wv0.x, acc1[2*q]);
            acc1[2*q+1] = fma2(a1, wv0.y, acc1[2*q+1]);
            ulonglong2 wv1 = wr1[q];
            acc0[2*q]   = fma2(b0, wv1.x, acc0[2*q]);
            acc0[2*q+1] = fma2(b0, wv1.y, acc0[2*q+1]);
            acc1[2*q]   = fma2(b1, wv1.x, acc1[2*q]);
            acc1[2*q+1] = fma2(b1, wv1.y, acc1[2*q+1]);
        }
    }
#pragma unroll
    for (int j = 0; j < 16; j++) {
        hp0[j] = tanh2p(acc0[j]);
        hp1[j] = tanh2p(acc1[j]);
    }
}

__global__ void __launch_bounds__(NTHREADS) pfnn_kernel(
    const float* __restrict__ x,
    const float* __restrict__ gW0, const float* __restrict__ gb0,
    const float* __restrict__ gW1, const float* __restrict__ gb1,
    const float* __restrict__ gW2, const float* __restrict__ gb2,
    const float* __restrict__ gW3, const float* __restrict__ gb3,
    float* __restrict__ out, int n) {
    __shared__ __align__(16) float sW0[NB][DIN][HID];
    __shared__ __align__(16) float sb0[NB][HID];
    __shared__ __align__(16) float sW1[NB][HID][HID];
    __shared__ __align__(16) float sb1[NB][HID];
    __shared__ __align__(16) float sW2[NB][HID][HID];
    __shared__ __align__(16) float sb2[NB][HID];
    __shared__ __align__(16) float sW3[NB][HID];
    __shared__ __align__(16) float sb3[NB];

    const int tid = threadIdx.x;
    {   // stage weights: big matrices vectorized
        const float4* g1 = (const float4*)gW1;
        const float4* g2 = (const float4*)gW2;
        float4* s1 = (float4*)&sW1[0][0][0];
        float4* s2 = (float4*)&sW2[0][0][0];
        for (int i = tid; i < NB * HID * HID / 4; i += NTHREADS) { s1[i] = g1[i]; s2[i] = g2[i]; }
        for (int i = tid; i < NB * DIN * HID; i += NTHREADS) (&sW0[0][0][0])[i] = gW0[i];
        for (int i = tid; i < NB * HID; i += NTHREADS) {
            (&sb0[0][0])[i] = gb0[i];
            (&sb1[0][0])[i] = gb1[i];
            (&sb2[0][0])[i] = gb2[i];
            (&sW3[0][0])[i] = gW3[i];
        }
        if (tid < NB) sb3[tid] = gb3[tid];
    }
    __syncthreads();

    const int p0 = blockIdx.x * (2 * NTHREADS) + tid;
    if (p0 >= n) return;
    int p1 = p0 + NTHREADS;
    const bool v1 = (p1 < n);
    if (!v1) p1 = p0;

    const float x00 = x[p0 * 3 + 0], x01 = x[p0 * 3 + 1], x02 = x[p0 * 3 + 2];
    const float x10 = x[p1 * 3 + 0], x11 = x[p1 * 3 + 1], x12 = x[p1 * 3 + 2];
    const ull xa0 = pack2(x00, x00), xa1 = pack2(x01, x01), xa2 = pack2(x02, x02);
    const ull xb0 = pack2(x10, x10), xb1 = pack2(x11, x11), xb2 = pack2(x12, x12);

    float o0[NB], o1[NB];

#pragma unroll 1
    for (int b = 0; b < NB; ++b) {
        // ---- layer 0: 3 -> 32, tanh ----
        ull hp0[16], hp1[16];
        {
            ull acc0[16], acc1[16];
            const ulonglong2* bb = (const ulonglong2*)sb0[b];
#pragma unroll
            for (int q = 0; q < 8; q++) {
                ulonglong2 t = bb[q];
                acc0[2*q] = t.x; acc0[2*q+1] = t.y;
                acc1[2*q] = t.x; acc1[2*q+1] = t.y;
            }
            const ulonglong2* w0r = (const ulonglong2*)sW0[b][0];
            const ulonglong2* w1r = (const ulonglong2*)sW0[b][1];
            const ulonglong2* w2r = (const ulonglong2*)sW0[b][2];
#pragma unroll
            for (int q = 0; q < 8; q++) {
                ulonglong2 wv0 = w0r[q];
                acc0[2*q]   = fma2(xa0, wv0.x, acc0[2*q]);
                acc0[2*q+1] = fma2(xa0, wv0.y, acc0[2*q+1]);
                acc1[2*q]   = fma2(xb0, wv0.x, acc1[2*q]);
                acc1[2*q+1] = fma2(xb0, wv0.y, acc1[2*q+1]);
                ulonglong2 wv1 = w1r[q];
                acc0[2*q]   = fma2(xa1, wv1.x, acc0[2*q]);
                acc0[2*q+1] = fma2(xa1, wv1.y, acc0[2*q+1]);
                acc1[2*q]   = fma2(xb1, wv1.x, acc1[2*q]);
                acc1[2*q+1] = fma2(xb1, wv1.y, acc1[2*q+1]);
                ulonglong2 wv2 = w2r[q];
                acc0[2*q]   = fma2(xa2, wv2.x, acc0[2*q]);
                acc0[2*q+1] = fma2(xa2, wv2.y, acc0[2*q+1]);
                acc1[2*q]   = fma2(xb2, wv2.x, acc1[2*q]);
                acc1[2*q+1] = fma2(xb2, wv2.y, acc1[2*q+1]);
            }
#pragma unroll
            for (int j = 0; j < 16; j++) {
                hp0[j] = tanh2p(acc0[j]);
                hp1[j] = tanh2p(acc1[j]);
            }
        }

        // ---- layers 1, 2: 32 -> 32, tanh ----
        dense32x2(&sW1[b][0][0], sb1[b], hp0, hp1);
        dense32x2(&sW2[b][0][0], sb2[b], hp0, hp1);

        // ---- layer 3: 32 -> 1 (packed dot) ----
        {
            const ulonglong2* w3r = (const ulonglong2*)sW3[b];
            ull s0 = pack2(0.0f, 0.0f), s1 = pack2(0.0f, 0.0f);
#pragma unroll
            for (int q = 0; q < 8; q++) {
                ulonglong2 wv = w3r[q];
                s0 = fma2(hp0[2*q],   wv.x, s0);
                s0 = fma2(hp0[2*q+1], wv.y, s0);
                s1 = fma2(hp1[2*q],   wv.x, s1);
                s1 = fma2(hp1[2*q+1], wv.y, s1);
            }
            float a, c; unpack2(s0, a, c);
            o0[b] = sb3[b] + a + c;
            unpack2(s1, a, c);
            o1[b] = sb3[b] + a + c;
        }
    }

    float4 r0 = make_float4(o0[0], o0[1], o0[2], o0[3]);
    ((float4*)out)[p0] = r0;
    if (v1) {
        float4 r1 = make_float4(o1[0], o1[1], o1[2], o1[3]);
        ((float4*)out)[p1] = r1;
    }
}

extern "C" void kernel_launch(void* const* d_in, const int* in_sizes, int n_in,
                              void* d_out, int out_size) {
    const float* x  = (const float*)d_in[0];
    const float* W0 = (const float*)d_in[1];
    const float* b0 = (const float*)d_in[2];
    const float* W1 = (const float*)d_in[3];
    const float* b1 = (const float*)d_in[4];
    const float* W2 = (const float*)d_in[5];
    const float* b2 = (const float*)d_in[6];
    const float* W3 = (const float*)d_in[7];
    const float* b3 = (const float*)d_in[8];
    float* out = (float*)d_out;

    const int n = in_sizes[0] / 3;
    const int pts_per_block = 2 * NTHREADS;
    const int blocks = (n + pts_per_block - 1) / pts_per_block;
    pfnn_kernel<<<blocks, NTHREADS>>>(x, W0, b0, W1, b1, W2, b2, W3, b3, out, n);
}

// round 4
// speedup vs baseline: 1.6719x; 1.6719x over previous
#include <cuda_runtime.h>

#define NTHREADS 128
#define HID 32
#define NB 4
#define DIN 3

typedef unsigned long long ull;

__device__ __forceinline__ ull fma2(ull a, ull b, ull c) {
    ull d; asm("fma.rn.f32x2 %0, %1, %2, %3;" : "=l"(d) : "l"(a), "l"(b), "l"(c)); return d;
}
__device__ __forceinline__ ull pack2(float lo, float hi) {
    ull r; asm("mov.b64 %0, {%1, %2};" : "=l"(r) : "f"(lo), "f"(hi)); return r;
}
__device__ __forceinline__ void unpack2(ull v, float& lo, float& hi) {
    asm("mov.b64 {%0, %1}, %2;" : "=f"(lo), "=f"(hi) : "l"(v));
}
__device__ __forceinline__ float ex2a(float x) {
    float y; asm("ex2.approx.f32 %0, %1;" : "=f"(y) : "f"(x)); return y;
}
__device__ __forceinline__ float rcpa(float x) {
    float y; asm("rcp.approx.f32 %0, %1;" : "=f"(y) : "f"(x)); return y;
}

// Weights/biases of layers 0..2 are pre-scaled by C=2*log2(e) at staging time,
// so the accumulator already holds C*z and tanh(z) = 1 - 2/(exp2(C*z)+1).
// Saturates correctly: z>>0 -> ex2=inf -> rcp=0 -> 1 ; z<<0 -> ex2=0 -> rcp(1)=1 -> -1.
__device__ __forceinline__ float tanh_pre(float a) {
    float y = ex2a(a);
    float r = rcpa(y + 1.0f);
    return fmaf(r, -2.0f, 1.0f);
}

// In-place 32->32 dense + tanh on packed hidden state hp[16] (pairs).
// w is [32][32] d-major (pre-scaled), bias pre-scaled.
__device__ __forceinline__ void dense32(const float* __restrict__ w,
                                        const float* __restrict__ bias,
                                        ull* __restrict__ hp) {
    ull acc[16];
    const ulonglong2* bb = (const ulonglong2*)bias;
#pragma unroll
    for (int q = 0; q < 8; q++) {
        ulonglong2 t = bb[q];
        acc[2 * q] = t.x; acc[2 * q + 1] = t.y;
    }
#pragma unroll
    for (int j = 0; j < 16; j++) {
        float l, u; unpack2(hp[j], l, u);
        ull hl = pack2(l, l), hu = pack2(u, u);
        const ulonglong2* r0 = (const ulonglong2*)(w + (2 * j) * HID);
        const ulonglong2* r1 = (const ulonglong2*)(w + (2 * j + 1) * HID);
#pragma unroll
        for (int q = 0; q < 8; q++) {
            ulonglong2 w0 = r0[q];
            acc[2 * q]     = fma2(hl, w0.x, acc[2 * q]);
            acc[2 * q + 1] = fma2(hl, w0.y, acc[2 * q + 1]);
            ulonglong2 w1 = r1[q];
            acc[2 * q]     = fma2(hu, w1.x, acc[2 * q]);
            acc[2 * q + 1] = fma2(hu, w1.y, acc[2 * q + 1]);
        }
    }
#pragma unroll
    for (int j = 0; j < 16; j++) {
        float a, b; unpack2(acc[j], a, b);
        hp[j] = pack2(tanh_pre(a), tanh_pre(b));
    }
}

__global__ void __launch_bounds__(NTHREADS, 5) pfnn_kernel(
    const float* __restrict__ x,
    const float* __restrict__ gW0, const float* __restrict__ gb0,
    const float* __restrict__ gW1, const float* __restrict__ gb1,
    const float* __restrict__ gW2, const float* __restrict__ gb2,
    const float* __restrict__ gW3, const float* __restrict__ gb3,
    float* __restrict__ out, int n) {
    __shared__ __align__(16) float sW0[NB][DIN][HID];
    __shared__ __align__(16) float sb0[NB][HID];
    __shared__ __align__(16) float sW1[NB][HID][HID];
    __shared__ __align__(16) float sb1[NB][HID];
    __shared__ __align__(16) float sW2[NB][HID][HID];
    __shared__ __align__(16) float sb2[NB][HID];
    __shared__ __align__(16) float sW3[NB][HID];
    __shared__ __align__(16) float sb3[NB];

    const float C = 2.885390081777927f;  // 2*log2(e), folded into layers 0..2
    const int tid = threadIdx.x;
    {
        for (int i = tid; i < NB * HID * HID; i += NTHREADS) {
            (&sW1[0][0][0])[i] = gW1[i] * C;
            (&sW2[0][0][0])[i] = gW2[i] * C;
        }
        for (int i = tid; i < NB * DIN * HID; i += NTHREADS) (&sW0[0][0][0])[i] = gW0[i] * C;
        for (int i = tid; i < NB * HID; i += NTHREADS) {
            (&sb0[0][0])[i] = gb0[i] * C;
            (&sb1[0][0])[i] = gb1[i] * C;
            (&sb2[0][0])[i] = gb2[i] * C;
            (&sW3[0][0])[i] = gW3[i];
        }
        if (tid < NB) sb3[tid] = gb3[tid];
    }
    __syncthreads();

    const int idx = blockIdx.x * NTHREADS + tid;
    if (idx >= n) return;

    const float x0 = x[idx * 3 + 0];
    const float x1 = x[idx * 3 + 1];
    const float x2 = x[idx * 3 + 2];
    const ull xx0 = pack2(x0, x0);
    const ull xx1 = pack2(x1, x1);
    const ull xx2 = pack2(x2, x2);

    float o[NB];

#pragma unroll 1
    for (int b = 0; b < NB; ++b) {
        // ---- layer 0: 3 -> 32, tanh (into packed hp) ----
        ull hp[16];
        {
            ull acc[16];
            const ulonglong2* bb = (const ulonglong2*)sb0[b];
#pragma unroll
            for (int q = 0; q < 8; q++) {
                ulonglong2 t = bb[q];
                acc[2 * q] = t.x; acc[2 * q + 1] = t.y;
            }
            const ulonglong2* w0r = (const ulonglong2*)sW0[b][0];
            const ulonglong2* w1r = (const ulonglong2*)sW0[b][1];
            const ulonglong2* w2r = (const ulonglong2*)sW0[b][2];
#pragma unroll
            for (int q = 0; q < 8; q++) {
                ulonglong2 wv0 = w0r[q];
                acc[2 * q]     = fma2(xx0, wv0.x, acc[2 * q]);
                acc[2 * q + 1] = fma2(xx0, wv0.y, acc[2 * q + 1]);
                ulonglong2 wv1 = w1r[q];
                acc[2 * q]     = fma2(xx1, wv1.x, acc[2 * q]);
                acc[2 * q + 1] = fma2(xx1, wv1.y, acc[2 * q + 1]);
                ulonglong2 wv2 = w2r[q];
                acc[2 * q]     = fma2(xx2, wv2.x, acc[2 * q]);
                acc[2 * q + 1] = fma2(xx2, wv2.y, acc[2 * q + 1]);
            }
#pragma unroll
            for (int j = 0; j < 16; j++) {
                float a, c; unpack2(acc[j], a, c);
                hp[j] = pack2(tanh_pre(a), tanh_pre(c));
            }
        }

        // ---- layers 1, 2: 32 -> 32, tanh, in place ----
        dense32(&sW1[b][0][0], sb1[b], hp);
        dense32(&sW2[b][0][0], sb2[b], hp);

        // ---- layer 3: 32 -> 1 (packed dot, plain weights) ----
        {
            const ulonglong2* w3r = (const ulonglong2*)sW3[b];
            ull s = pack2(0.0f, 0.0f);
#pragma unroll
            for (int q = 0; q < 8; q++) {
                ulonglong2 wv = w3r[q];
                s = fma2(hp[2 * q],     wv.x, s);
                s = fma2(hp[2 * q + 1], wv.y, s);
            }
            float a, c; unpack2(s, a, c);
            o[b] = sb3[b] + a + c;
        }
    }

    ((float4*)out)[idx] = make_float4(o[0], o[1], o[2], o[3]);
}

extern "C" void kernel_launch(void* const* d_in, const int* in_sizes, int n_in,
                              void* d_out, int out_size) {
    const float* x  = (const float*)d_in[0];
    const float* W0 = (const float*)d_in[1];
    const float* b0 = (const float*)d_in[2];
    const float* W1 = (const float*)d_in[3];
    const float* b1 = (const float*)d_in[4];
    const float* W2 = (const float*)d_in[5];
    const float* b2 = (const float*)d_in[6];
    const float* W3 = (const float*)d_in[7];
    const float* b3 = (const float*)d_in[8];
    float* out = (float*)d_out;

    const int n = in_sizes[0] / 3;
    const int blocks = (n + NTHREADS - 1) / NTHREADS;
    pfnn_kernel<<<blocks, NTHREADS>>>(x, W0, b0, W1, b1, W2, b2, W3, b3, out, n);
}